// round 2
// baseline (speedup 1.0000x reference)
#include <cuda_runtime.h>
#include <cuda_bf16.h>
#include <math.h>

// ---------- scratch (device globals; no runtime allocation) ----------
__device__ float  g_y1[1024*200*8*64];   // [b][h][c][w]  elu(conv1)  419MB
__device__ float  g_y2[1024*16*200];     // [b][oc][h]
__device__ float  g_y3[1024*16*50];      // [b][c][h]
__device__ float  g_feat[16*100*1024];   // [c][f][b]
__device__ float  g_y[1024*16];          // [b][c]
__device__ double g_p1[256][16];
__device__ double g_p2[256][32];
__device__ double g_p3[256][32];
__device__ float  g_w2s[16*128], g_b2e[16];
__device__ float  g_a2[16], g_d2[16];
__device__ float  g_a3[16], g_d3[16];

__device__ __forceinline__ float sigm(float x){ return 1.f/(1.f+__expf(-x)); }
__device__ __forceinline__ float tanhfast(float x){ return 2.f/(1.f+__expf(-2.f*x))-1.f; }
__device__ __forceinline__ float eluf(float x){ return x>0.f ? x : expm1f(x); }

// ---------- zero stat partials ----------
__global__ void kZ(){
    int i = blockIdx.x*256 + threadIdx.x;
    if (i<4096) ((double*)g_p1)[i]=0.0;
    int j=i-4096;  if (j>=0 && j<8192) ((double*)g_p2)[j]=0.0;
    int k=i-12288; if (k>=0 && k<8192) ((double*)g_p3)[k]=0.0;
}

// ---------- k1: conv1 (101 taps along H) + ELU + BN1 stats ----------
// grid (8 h-chunks, 1024 b), block (32 w-pairs, 5 h-groups). Thread: 5 h x 8 oc x 2 w.
__global__ void __launch_bounds__(160) k1_conv1(const float* __restrict__ x,
                                                const float* __restrict__ c1w,
                                                const float* __restrict__ c1b){
    __shared__ float xs[125*64];
    __shared__ unsigned long long wdu[101*8];
    __shared__ float rs_[5][8], rq_[5][8];
    int b = blockIdx.y, chunk = blockIdx.x, h0 = chunk*25;
    int wt = threadIdx.x, hg = threadIdx.y, t = hg*32+wt;

    const float* xb = x + b*12800;
    for (int i=t;i<8000;i+=160){
        int row=i>>6, w=i&63, gr=h0-50+row;
        xs[i] = (gr>=0 && gr<200) ? xb[gr*64+w] : 0.f;
    }
    for (int i=t;i<808;i+=160){
        int k=i>>3, oc=i&7;
        float v=c1w[oc*101+k];
        unsigned long long p;
        asm("mov.b64 %0,{%1,%2};":"=l"(p):"f"(v),"f"(v));
        wdu[i]=p;
    }
    __syncthreads();

    const unsigned long long* xsu=(const unsigned long long*)xs;
    int basei = hg*5;
    unsigned long long W[5];
    #pragma unroll
    for (int j=0;j<4;j++) W[j]=xsu[(basei+j)*32+wt];
    unsigned long long acc[5][8];
    #pragma unroll
    for (int i=0;i<5;i++)
        #pragma unroll
        for (int o=0;o<8;o++) acc[i][o]=0ULL;

    for (int k5=0;k5<100;k5+=5){
        #pragma unroll
        for (int kk=0;kk<5;kk++){
            int k=k5+kk;
            W[(kk+4)%5]=xsu[(basei+k+4)*32+wt];
            #pragma unroll
            for (int o=0;o<8;o++){
                unsigned long long wv=wdu[k*8+o];
                #pragma unroll
                for (int i=0;i<5;i++)
                    asm("fma.rn.f32x2 %0,%1,%2,%0;":"+l"(acc[i][o]):"l"(W[(kk+i)%5]),"l"(wv));
            }
        }
    }
    { // k = 100: rows basei+100+i sit at slot i
        W[4]=xsu[(basei+104)*32+wt];
        #pragma unroll
        for (int o=0;o<8;o++){
            unsigned long long wv=wdu[800+o];
            #pragma unroll
            for (int i=0;i<5;i++)
                asm("fma.rn.f32x2 %0,%1,%2,%0;":"+l"(acc[i][o]):"l"(W[i]),"l"(wv));
        }
    }

    float s[8], qq[8];
    #pragma unroll
    for (int o=0;o<8;o++){ s[o]=0.f; qq[o]=0.f; }
    #pragma unroll
    for (int o=0;o<8;o++){
        float bo=c1b[o];
        #pragma unroll
        for (int i=0;i<5;i++){
            float lo,hi;
            asm("mov.b64 {%0,%1}, %2;":"=f"(lo),"=f"(hi):"l"(acc[i][o]));
            lo+=bo; hi+=bo;
            float elo=eluf(lo), ehi=eluf(hi);
            int h=h0+basei+i;
            *(float2*)&g_y1[((b*200+h)*8+o)*64 + 2*wt] = make_float2(elo,ehi);
            s[o]+=elo+ehi; qq[o]+=elo*elo+ehi*ehi;
        }
    }
    #pragma unroll
    for (int o=0;o<8;o++)
        for (int off=16;off;off>>=1){
            s[o]+=__shfl_xor_sync(0xffffffffu,s[o],off);
            qq[o]+=__shfl_xor_sync(0xffffffffu,qq[o],off);
        }
    if (wt==0){
        #pragma unroll
        for (int o=0;o<8;o++){ rs_[hg][o]=s[o]; rq_[hg][o]=qq[o]; }
    }
    __syncthreads();
    if (t<8){
        float S=0.f,Q=0.f;
        #pragma unroll
        for (int w=0;w<5;w++){ S+=rs_[w][t]; Q+=rq_[w][t]; }
        int slot=(b*8+chunk)&255;
        atomicAdd(&g_p1[slot][t*2],(double)S);
        atomicAdd(&g_p1[slot][t*2+1],(double)Q);
    }
}

// ---------- k2: BN1 coefficients folded into conv2 weights ----------
__global__ void k2_setup(const float* __restrict__ bn1w, const float* __restrict__ bn1b,
                         const float* __restrict__ c2w,  const float* __restrict__ c2b){
    __shared__ float a1s[8], d1s[8];
    int t=threadIdx.x;
    if (t<8){
        double s=0.0,q=0.0;
        for (int i=0;i<256;i++){ s+=g_p1[i][t*2]; q+=g_p1[i][t*2+1]; }
        const double N=13107200.0;
        double m=s/N, var=q/N-m*m;
        float a=bn1w[t]*(float)(1.0/sqrt(var));
        a1s[t]=a; d1s[t]=bn1b[t]-(float)m*a;
    }
    __syncthreads();
    for (int idx=t; idx<2048; idx+=256){
        int oc=idx>>7, m=idx&127, ic2=m>>6, g=oc>>2;
        g_w2s[idx]=c2w[(oc*2+ic2)*64+(m&63)]*a1s[g*2+ic2];
    }
    if (t<16){
        float acc=c2b[t]; int g=t>>2;
        for (int m=0;m<128;m++){
            int ic2=m>>6;
            acc += c2w[(t*2+ic2)*64+(m&63)]*d1s[g*2+ic2];
        }
        g_b2e[t]=acc;
    }
}

// ---------- k3: conv2 (BN1 folded) + ELU + BN2 stats ----------
__global__ void __launch_bounds__(160) k3_conv2(){
    __shared__ float tile[5120], ws[2048], be[16], redS[16], redQ[16];
    int b=blockIdx.y, h0=blockIdx.x*10, t=threadIdx.x;
    const float4* src=(const float4*)(g_y1+(size_t)(b*200+h0)*512);
    float4* td=(float4*)tile;
    for (int i=t;i<1280;i+=160) td[i]=src[i];
    for (int i=t;i<2048;i+=160) ws[i]=g_w2s[i];
    if (t<16){ be[t]=g_b2e[t]; redS[t]=0.f; redQ[t]=0.f; }
    __syncthreads();
    int hh=t/16, oc=t&15, g=oc>>2;
    const float4* sp=(const float4*)(tile+hh*512+g*128);
    const float4* wp=(const float4*)(ws+oc*128);
    float acc=be[oc];
    #pragma unroll
    for (int m=0;m<32;m++){
        float4 a=sp[m], w=wp[m];
        acc += a.x*w.x+a.y*w.y+a.z*w.z+a.w*w.w;
    }
    float v=eluf(acc);
    g_y2[(b*16+oc)*200+h0+hh]=v;
    atomicAdd(&redS[oc],v); atomicAdd(&redQ[oc],v*v);
    __syncthreads();
    if (t<16){
        int slot=(b*20+blockIdx.x)&255;
        atomicAdd(&g_p2[slot][t*2],(double)redS[t]);
        atomicAdd(&g_p2[slot][t*2+1],(double)redQ[t]);
    }
}

__global__ void k4_bn2(const float* __restrict__ bnw, const float* __restrict__ bnb){
    int t=threadIdx.x;
    if (t<16){
        double s=0.0,q=0.0;
        for (int i=0;i<256;i++){ s+=g_p2[i][t*2]; q+=g_p2[i][t*2+1]; }
        const double N=204800.0;
        double m=s/N, var=q/N-m*m;
        float a=bnw[t]*(float)(1.0/sqrt(var));
        g_a2[t]=a; g_d2[t]=bnb[t]-(float)m*a;
    }
}
__global__ void k6_bn3(const float* __restrict__ bnw, const float* __restrict__ bnb){
    int t=threadIdx.x;
    if (t<16){
        double s=0.0,q=0.0;
        for (int i=0;i<256;i++){ s+=g_p3[i][t*2]; q+=g_p3[i][t*2+1]; }
        const double N=51200.0;
        double m=s/N, var=q/N-m*m;
        float a=bnw[t]*(float)(1.0/sqrt(var));
        g_a3[t]=a; g_d3[t]=bnb[t]-(float)m*a;
    }
}

// ---------- k5: BN2+pool4 + conv3 + ELU + convp + ELU + BN3 stats ----------
__global__ void k5_conv3p(const float* __restrict__ c3w, const float* __restrict__ c3b,
                          const float* __restrict__ cpw, const float* __restrict__ cpb){
    __shared__ float s2[3200], t1[800], u[800], redS[16], redQ[16];
    int b=blockIdx.x, t=threadIdx.x;
    const float* src=g_y2+b*3200;
    for (int i=t;i<3200;i+=256) s2[i]=src[i];
    if (t<16){ redS[t]=0.f; redQ[t]=0.f; }
    __syncthreads();
    for (int i=t;i<800;i+=256){
        int cch=i/50, hh=i%50;
        float a=g_a2[cch], d=g_d2[cch];
        const float* p=&s2[cch*200+hh*4];
        t1[i]=fmaxf(fmaxf(fmaf(a,p[0],d),fmaf(a,p[1],d)),
                    fmaxf(fmaf(a,p[2],d),fmaf(a,p[3],d)));
    }
    __syncthreads();
    for (int i=t;i<800;i+=256){
        int oc=i/50, h=i%50, g=oc>>1;
        float acc=c3b[oc];
        #pragma unroll
        for (int ic2=0;ic2<2;ic2++){
            const float* wr=c3w+(oc*2+ic2)*25;
            const float* tr=t1+(g*2+ic2)*50;
            #pragma unroll
            for (int k=0;k<25;k++){
                int hp=h+k-12;
                if (hp>=0 && hp<50) acc=fmaf(wr[k],tr[hp],acc);
            }
        }
        u[i]=eluf(acc);
    }
    __syncthreads();
    for (int i=t;i<800;i+=256){
        int o=i/50, h=i%50;
        float acc=cpb[o];
        #pragma unroll
        for (int k=0;k<16;k++) acc=fmaf(cpw[o*16+k],u[k*50+h],acc);
        float v=eluf(acc);
        g_y3[b*800+o*50+h]=v;
        atomicAdd(&redS[o],v); atomicAdd(&redQ[o],v*v);
    }
    __syncthreads();
    if (t<16){
        int slot=b&255;
        atomicAdd(&g_p3[slot][t*2],(double)redS[t]);
        atomicAdd(&g_p3[slot][t*2+1],(double)redQ[t]);
    }
}

// ---------- k7: LSTM. BN3+pool2 on the fly; fwd full scan; bwd is ONE step ----------
// grid 512 (16 c x 32 b-blocks of 32), 128 threads: (row r=t/4, gate-quarter q=t%4)
__global__ void __launch_bounds__(128) k7_lstm(const float* __restrict__ wih,
                                               const float* __restrict__ whh,
                                               const float* __restrict__ bih,
                                               const float* __restrict__ bhh){
    extern __shared__ float sm[];
    float* whhs = sm;            // 200*52 = 10400
    float* wihs = sm+10400;      // 200
    float* biass= sm+10600;      // 200
    float* gates= sm+10800;      // 32*200 = 6400
    float* hsm  = sm+17200;      // 1600
    float* csm  = sm+18800;      // 1600
    float* xsm  = sm+20400;      // 800  -> 21200 floats = 84800 B
    int c=blockIdx.x>>5, b0=(blockIdx.x&31)<<5, t=threadIdx.x;
    int base=(c*2)*200;

    for (int i=t;i<10000;i+=128){ int j=i/50,k=i%50; whhs[j*52+k]=whh[(base+j)*50+k]; }
    for (int i=t;i<200;i+=128){ wihs[i]=wih[base+i]; biass[i]=bih[base+i]+bhh[base+i]; }
    {
        float a3=g_a3[c], d3=g_d3[c];
        for (int i=t;i<800;i+=128){
            int r=i/25, tt=i%25;
            const float* yp=g_y3+((b0+r)*16+c)*50;
            xsm[i]=fmaxf(fmaf(a3,yp[2*tt],d3), fmaf(a3,yp[2*tt+1],d3));
        }
    }
    for (int i=t;i<1600;i+=128){ hsm[i]=0.f; csm[i]=0.f; }
    __syncthreads();

    int r=t>>2, q=t&3;
    float* grow=gates+r*200;
    for (int step=0;step<25;step++){
        float hr[50];
        #pragma unroll
        for (int k=0;k<50;k++) hr[k]=hsm[r*50+k];
        float xv=xsm[r*25+step];
        for (int jj=0;jj<50;jj++){
            int j=q*50+jj;
            float acc=fmaf(xv,wihs[j],biass[j]);
            const float4* w4=(const float4*)(whhs+j*52);
            #pragma unroll
            for (int k4=0;k4<12;k4++){
                float4 w=w4[k4];
                acc=fmaf(w.x,hr[4*k4],acc);   acc=fmaf(w.y,hr[4*k4+1],acc);
                acc=fmaf(w.z,hr[4*k4+2],acc); acc=fmaf(w.w,hr[4*k4+3],acc);
            }
            acc=fmaf(whhs[j*52+48],hr[48],acc);
            acc=fmaf(whhs[j*52+49],hr[49],acc);
            grow[j]=(q==2)?tanhfast(acc):sigm(acc);
        }
        __syncthreads();
        for (int i=t;i<1600;i+=128){
            int rr=i/50, k=i%50;
            const float* gr=gates+rr*200;
            float cn=fmaf(gr[50+k],csm[i],gr[k]*gr[100+k]);
            csm[i]=cn;
            float hn=gr[150+k]*tanhfast(cn);
            hsm[i]=hn;
            if (step==24) g_feat[(c*100+k)*1024 + b0+rr]=hn;
        }
        __syncthreads();
    }
    // backward direction: only first step of reversed scan used (x = t=T-1, zero state)
    int bb=(c*2+1)*200;
    for (int i=t;i<1600;i+=128){
        int rr=i/50, k=i%50;
        float xv=xsm[rr*25+24];
        float ig=sigm   (fmaf(xv,wih[bb+k],     bih[bb+k]     +bhh[bb+k]));
        float gg=tanhfast(fmaf(xv,wih[bb+100+k],bih[bb+100+k]+bhh[bb+100+k]));
        float oo=sigm   (fmaf(xv,wih[bb+150+k],bih[bb+150+k]+bhh[bb+150+k]));
        g_feat[(c*100+50+k)*1024 + b0+rr]=oo*tanhfast(ig*gg);
    }
}

// ---------- k8: per-channel head BN + linear + sigmoid ----------
__global__ void k8_head(const float* __restrict__ hbnw, const float* __restrict__ hbnb,
                        const float* __restrict__ hlw,  const float* __restrict__ hlb){
    __shared__ float coef[100], dterm[104];
    __shared__ float Cs;
    int c=blockIdx.x, t=threadIdx.x, lane=t&31, w=t>>5;   // 256 threads, 8 warps
    for (int f=t;f<104;f+=256) dterm[f]=0.f;
    __syncthreads();
    for (int f=w; f<100; f+=8){
        const float* p=g_feat+(c*100+f)*1024;
        float s=0.f,q=0.f;
        for (int j=lane;j<1024;j+=32){ float v=p[j]; s+=v; q+=v*v; }
        for (int off=16;off;off>>=1){
            s+=__shfl_xor_sync(0xffffffffu,s,off);
            q+=__shfl_xor_sync(0xffffffffu,q,off);
        }
        if (lane==0){
            float m=s*(1.f/1024.f), var=q*(1.f/1024.f)-m*m;
            float a=hbnw[c*100+f]*rsqrtf(var);
            float d=hbnb[c*100+f]-m*a;
            float lw=hlw[c*100+f];
            coef[f]=a*lw;
            dterm[f]=d*lw;
        }
    }
    __syncthreads();
    if (t==0){
        float s=hlb[c];
        for (int f=0;f<100;f++) s+=dterm[f];
        Cs=s;
    }
    __syncthreads();
    float C=Cs;
    for (int b=t;b<1024;b+=256){
        float acc=C;
        #pragma unroll 4
        for (int f=0;f<100;f++) acc+=g_feat[(c*100+f)*1024+b]*coef[f];
        g_y[b*16+c]=sigm(acc);
    }
}

// ---------- k9: final BN over batch + linear + sigmoid ----------
__global__ void k9_final(const float* __restrict__ fbnw, const float* __restrict__ fbnb,
                         const float* __restrict__ flw,  const float* __restrict__ flb,
                         float* __restrict__ out){
    __shared__ float ss[16], sq[16], cf[16];
    __shared__ float Cs;
    int t=threadIdx.x, lane=t&31;
    if (t<16){ ss[t]=0.f; sq[t]=0.f; }
    __syncthreads();
    float yv[16];
    #pragma unroll
    for (int c=0;c<16;c++) yv[c]=g_y[t*16+c];
    #pragma unroll
    for (int c=0;c<16;c++){
        float s=yv[c], q=yv[c]*yv[c];
        for (int off=16;off;off>>=1){
            s+=__shfl_xor_sync(0xffffffffu,s,off);
            q+=__shfl_xor_sync(0xffffffffu,q,off);
        }
        if (lane==0){ atomicAdd(&ss[c],s); atomicAdd(&sq[c],q); }
    }
    __syncthreads();
    if (t<16){
        float m=ss[t]*(1.f/1024.f), var=sq[t]*(1.f/1024.f)-m*m;
        float a=fbnw[t]*rsqrtf(var);
        float d=fbnb[t]-m*a;
        cf[t]=a*flw[t];
        ss[t]=d*flw[t];
    }
    __syncthreads();
    if (t==0){
        float s=flb[0];
        #pragma unroll
        for (int c=0;c<16;c++) s+=ss[c];
        Cs=s;
    }
    __syncthreads();
    float acc=Cs;
    #pragma unroll
    for (int c=0;c<16;c++) acc+=yv[c]*cf[c];
    out[t]=sigm(acc);
}

extern "C" void kernel_launch(void* const* d_in, const int* in_sizes, int n_in,
                              void* d_out, int out_size){
    const float* x    =(const float*)d_in[0];
    const float* c1w  =(const float*)d_in[1];
    const float* c1b  =(const float*)d_in[2];
    const float* bn1w =(const float*)d_in[3];
    const float* bn1b =(const float*)d_in[4];
    const float* c2w  =(const float*)d_in[5];
    const float* c2b  =(const float*)d_in[6];
    const float* bn2w =(const float*)d_in[7];
    const float* bn2b =(const float*)d_in[8];
    const float* c3w  =(const float*)d_in[9];
    const float* c3b  =(const float*)d_in[10];
    const float* bn3w =(const float*)d_in[11];
    const float* bn3b =(const float*)d_in[12];
    const float* cpw  =(const float*)d_in[13];
    const float* cpb  =(const float*)d_in[14];
    const float* wih  =(const float*)d_in[15];
    const float* whh  =(const float*)d_in[16];
    const float* bih  =(const float*)d_in[17];
    const float* bhh  =(const float*)d_in[18];
    const float* hbnw =(const float*)d_in[19];
    const float* hbnb =(const float*)d_in[20];
    const float* hlw  =(const float*)d_in[21];
    const float* hlb  =(const float*)d_in[22];
    const float* fbnw =(const float*)d_in[23];
    const float* fbnb =(const float*)d_in[24];
    const float* flw  =(const float*)d_in[25];
    const float* flb  =(const float*)d_in[26];
    float* out=(float*)d_out;

    cudaFuncSetAttribute(k7_lstm, cudaFuncAttributeMaxDynamicSharedMemorySize, 84800);

    kZ<<<80,256>>>();
    k1_conv1<<<dim3(8,1024), dim3(32,5)>>>(x,c1w,c1b);
    k2_setup<<<1,256>>>(bn1w,bn1b,c2w,c2b);
    k3_conv2<<<dim3(20,1024),160>>>();
    k4_bn2<<<1,32>>>(bn2w,bn2b);
    k5_conv3p<<<1024,256>>>(c3w,c3b,cpw,cpb);
    k6_bn3<<<1,32>>>(bn3w,bn3b);
    k7_lstm<<<512,128,84800>>>(wih,whh,bih,bhh);
    k8_head<<<16,256>>>(hbnw,hbnb,hlw,hlb);
    k9_final<<<1,1024>>>(fbnw,fbnb,flw,flb,out);
}

// round 3
// speedup vs baseline: 1.1961x; 1.1961x over previous
#include <cuda_runtime.h>
#include <cuda_bf16.h>
#include <math.h>

// ---------- scratch (device globals; no runtime allocation) ----------
__device__ float  g_y1[1024*200*8*64];   // [b][h][c][w]  elu(conv1)  419MB
__device__ float  g_y2[1024*200*16];     // [b][h][oc]
__device__ float  g_y3[1024*16*50];      // [b][c][h]
__device__ float  g_feat[16*100*1024];   // [c][f][b]
__device__ float  g_y[1024*16];          // [b][c]
__device__ double g_p1[256][16];
__device__ double g_p2[256][32];
__device__ double g_p3[256][32];
__device__ float  g_w2s[16*128], g_b2e[16];
__device__ float  g_a2[16], g_d2[16];
__device__ float  g_a3[16], g_d3[16];

__device__ __forceinline__ float sigm(float x){ return 1.f/(1.f+__expf(-x)); }
__device__ __forceinline__ float tanhfast(float x){ return 2.f/(1.f+__expf(-2.f*x))-1.f; }
__device__ __forceinline__ float eluf(float x){ return x>0.f ? x : expm1f(x); }

// ---------- zero stat partials ----------
__global__ void kZ(){
    int i = blockIdx.x*256 + threadIdx.x;
    if (i<4096) ((double*)g_p1)[i]=0.0;
    int j=i-4096;  if (j>=0 && j<8192) ((double*)g_p2)[j]=0.0;
    int k=i-12288; if (k>=0 && k<8192) ((double*)g_p3)[k]=0.0;
}

// ---------- k1: conv1 (101 taps along H) + ELU + BN1 stats ----------
__global__ void __launch_bounds__(160) k1_conv1(const float* __restrict__ x,
                                                const float* __restrict__ c1w,
                                                const float* __restrict__ c1b){
    __shared__ float xs[125*64];
    __shared__ unsigned long long wdu[101*8];
    __shared__ float rs_[5][8], rq_[5][8];
    int b = blockIdx.y, chunk = blockIdx.x, h0 = chunk*25;
    int wt = threadIdx.x, hg = threadIdx.y, t = hg*32+wt;

    const float* xb = x + b*12800;
    for (int i=t;i<8000;i+=160){
        int row=i>>6, w=i&63, gr=h0-50+row;
        xs[i] = (gr>=0 && gr<200) ? xb[gr*64+w] : 0.f;
    }
    for (int i=t;i<808;i+=160){
        int k=i>>3, oc=i&7;
        float v=c1w[oc*101+k];
        unsigned long long p;
        asm("mov.b64 %0,{%1,%2};":"=l"(p):"f"(v),"f"(v));
        wdu[i]=p;
    }
    __syncthreads();

    const unsigned long long* xsu=(const unsigned long long*)xs;
    int basei = hg*5;
    unsigned long long W[5];
    #pragma unroll
    for (int j=0;j<4;j++) W[j]=xsu[(basei+j)*32+wt];
    unsigned long long acc[5][8];
    #pragma unroll
    for (int i=0;i<5;i++)
        #pragma unroll
        for (int o=0;o<8;o++) acc[i][o]=0ULL;

    for (int k5=0;k5<100;k5+=5){
        #pragma unroll
        for (int kk=0;kk<5;kk++){
            int k=k5+kk;
            W[(kk+4)%5]=xsu[(basei+k+4)*32+wt];
            #pragma unroll
            for (int o=0;o<8;o++){
                unsigned long long wv=wdu[k*8+o];
                #pragma unroll
                for (int i=0;i<5;i++)
                    asm("fma.rn.f32x2 %0,%1,%2,%0;":"+l"(acc[i][o]):"l"(W[(kk+i)%5]),"l"(wv));
            }
        }
    }
    {
        W[4]=xsu[(basei+104)*32+wt];
        #pragma unroll
        for (int o=0;o<8;o++){
            unsigned long long wv=wdu[800+o];
            #pragma unroll
            for (int i=0;i<5;i++)
                asm("fma.rn.f32x2 %0,%1,%2,%0;":"+l"(acc[i][o]):"l"(W[i]),"l"(wv));
        }
    }

    float s[8], qq[8];
    #pragma unroll
    for (int o=0;o<8;o++){ s[o]=0.f; qq[o]=0.f; }
    #pragma unroll
    for (int o=0;o<8;o++){
        float bo=c1b[o];
        #pragma unroll
        for (int i=0;i<5;i++){
            float lo,hi;
            asm("mov.b64 {%0,%1}, %2;":"=f"(lo),"=f"(hi):"l"(acc[i][o]));
            lo+=bo; hi+=bo;
            float elo=eluf(lo), ehi=eluf(hi);
            int h=h0+basei+i;
            *(float2*)&g_y1[((b*200+h)*8+o)*64 + 2*wt] = make_float2(elo,ehi);
            s[o]+=elo+ehi; qq[o]+=elo*elo+ehi*ehi;
        }
    }
    #pragma unroll
    for (int o=0;o<8;o++)
        for (int off=16;off;off>>=1){
            s[o]+=__shfl_xor_sync(0xffffffffu,s[o],off);
            qq[o]+=__shfl_xor_sync(0xffffffffu,qq[o],off);
        }
    if (wt==0){
        #pragma unroll
        for (int o=0;o<8;o++){ rs_[hg][o]=s[o]; rq_[hg][o]=qq[o]; }
    }
    __syncthreads();
    if (t<8){
        float S=0.f,Q=0.f;
        #pragma unroll
        for (int w=0;w<5;w++){ S+=rs_[w][t]; Q+=rq_[w][t]; }
        int slot=(b*8+chunk)&255;
        atomicAdd(&g_p1[slot][t*2],(double)S);
        atomicAdd(&g_p1[slot][t*2+1],(double)Q);
    }
}

// ---------- k2: BN1 coefficients folded into conv2 weights ----------
__global__ void k2_setup(const float* __restrict__ bn1w, const float* __restrict__ bn1b,
                         const float* __restrict__ c2w,  const float* __restrict__ c2b){
    __shared__ float a1s[8], d1s[8];
    int t=threadIdx.x;
    if (t<8){
        double s=0.0,q=0.0;
        for (int i=0;i<256;i++){ s+=g_p1[i][t*2]; q+=g_p1[i][t*2+1]; }
        const double N=13107200.0;
        double m=s/N, var=q/N-m*m;
        float a=bn1w[t]*(float)(1.0/sqrt(var));
        a1s[t]=a; d1s[t]=bn1b[t]-(float)m*a;
    }
    __syncthreads();
    for (int idx=t; idx<2048; idx+=256){
        int oc=idx>>7, m=idx&127, ic2=m>>6, g=oc>>2;
        g_w2s[idx]=c2w[(oc*2+ic2)*64+(m&63)]*a1s[g*2+ic2];
    }
    if (t<16){
        float acc=c2b[t]; int g=t>>2;
        for (int m=0;m<128;m++){
            int ic2=m>>6;
            acc += c2w[(t*2+ic2)*64+(m&63)]*d1s[g*2+ic2];
        }
        g_b2e[t]=acc;
    }
}

// ---------- k3: conv2 (BN1 folded) + ELU, streaming, warp-per-row ----------
// grid 1024 (b), 256 threads (8 warps). Warp handles rows h = w, w+8, ...
__global__ void __launch_bounds__(256) k3_conv2(){
    __shared__ float be[16];
    int b=blockIdx.x, t=threadIdx.x, w=t>>5, l=t&31;
    if (t<16) be[t]=g_b2e[t];
    // weights: at chunk s4, lane l covers group s4 positions 4l..4l+3
    float4 wr[4][4];
    const float4* w4=(const float4*)g_w2s;
    #pragma unroll
    for (int s4=0;s4<4;s4++)
        #pragma unroll
        for (int j=0;j<4;j++) wr[s4][j]=w4[(4*s4+j)*32+l];
    __syncthreads();
    const float4* ybase=(const float4*)(g_y1+(size_t)b*102400);
    float4 v[4];
    int h=w;
    #pragma unroll
    for (int s4=0;s4<4;s4++) v[s4]=ybase[h*128+s4*32+l];
    for (; h<200; h+=8){
        float4 vn[4];
        int hn=h+8;
        if (hn<200){
            #pragma unroll
            for (int s4=0;s4<4;s4++) vn[s4]=ybase[hn*128+s4*32+l];
        }
        float p[4][4];
        #pragma unroll
        for (int s4=0;s4<4;s4++){
            #pragma unroll
            for (int j=0;j<4;j++){
                float4 wv=wr[s4][j];
                p[s4][j]=v[s4].x*wv.x+v[s4].y*wv.y+v[s4].z*wv.z+v[s4].w*wv.w;
            }
        }
        #pragma unroll
        for (int off=1;off<32;off<<=1)
            #pragma unroll
            for (int s4=0;s4<4;s4++)
                #pragma unroll
                for (int j=0;j<4;j++)
                    p[s4][j]+=__shfl_xor_sync(0xffffffffu,p[s4][j],off);
        if (l==0){
            float4 o0,o1,o2,o3;
            o0.x=eluf(p[0][0]+be[0]);  o0.y=eluf(p[0][1]+be[1]);
            o0.z=eluf(p[0][2]+be[2]);  o0.w=eluf(p[0][3]+be[3]);
            o1.x=eluf(p[1][0]+be[4]);  o1.y=eluf(p[1][1]+be[5]);
            o1.z=eluf(p[1][2]+be[6]);  o1.w=eluf(p[1][3]+be[7]);
            o2.x=eluf(p[2][0]+be[8]);  o2.y=eluf(p[2][1]+be[9]);
            o2.z=eluf(p[2][2]+be[10]); o2.w=eluf(p[2][3]+be[11]);
            o3.x=eluf(p[3][0]+be[12]); o3.y=eluf(p[3][1]+be[13]);
            o3.z=eluf(p[3][2]+be[14]); o3.w=eluf(p[3][3]+be[15]);
            float4* dst=(float4*)(g_y2+((size_t)b*200+h)*16);
            dst[0]=o0; dst[1]=o1; dst[2]=o2; dst[3]=o3;
        }
        #pragma unroll
        for (int s4=0;s4<4;s4++) v[s4]=vn[s4];
    }
}

// ---------- k3b: BN2 stats over y2 (13 MB, trivial) ----------
__global__ void k3b_stats(){
    __shared__ float sS[16], sQ[16];
    int t=threadIdx.x, c=t&15, sub=t>>4;           // 256 thr: 16 chunks x 16 c
    if (t<16){ sS[t]=0.f; sQ[t]=0.f; }
    __syncthreads();
    int chunk = blockIdx.x*16 + sub;               // 4096 chunks of 50 rows
    const float* p = g_y2 + (size_t)chunk*800 + c;
    float s=0.f,q=0.f;
    #pragma unroll 5
    for (int r=0;r<50;r++){ float v=p[r*16]; s+=v; q+=v*v; }
    atomicAdd(&sS[c],s); atomicAdd(&sQ[c],q);
    __syncthreads();
    if (t<16){
        atomicAdd(&g_p2[blockIdx.x][t*2],(double)sS[t]);
        atomicAdd(&g_p2[blockIdx.x][t*2+1],(double)sQ[t]);
    }
}

__global__ void k4_bn2(const float* __restrict__ bnw, const float* __restrict__ bnb){
    int t=threadIdx.x;
    if (t<16){
        double s=0.0,q=0.0;
        for (int i=0;i<256;i++){ s+=g_p2[i][t*2]; q+=g_p2[i][t*2+1]; }
        const double N=204800.0;
        double m=s/N, var=q/N-m*m;
        float a=bnw[t]*(float)(1.0/sqrt(var));
        g_a2[t]=a; g_d2[t]=bnb[t]-(float)m*a;
    }
}
__global__ void k6_bn3(const float* __restrict__ bnw, const float* __restrict__ bnb){
    int t=threadIdx.x;
    if (t<16){
        double s=0.0,q=0.0;
        for (int i=0;i<256;i++){ s+=g_p3[i][t*2]; q+=g_p3[i][t*2+1]; }
        const double N=51200.0;
        double m=s/N, var=q/N-m*m;
        float a=bnw[t]*(float)(1.0/sqrt(var));
        g_a3[t]=a; g_d3[t]=bnb[t]-(float)m*a;
    }
}

// ---------- k5: BN2+pool4 + conv3 + ELU + convp + ELU + BN3 stats ----------
__global__ void k5_conv3p(const float* __restrict__ c3w, const float* __restrict__ c3b,
                          const float* __restrict__ cpw, const float* __restrict__ cpb){
    __shared__ float s2[3200], t1[800], u[800], redS[16], redQ[16];
    int b=blockIdx.x, t=threadIdx.x;
    const float* src=g_y2+(size_t)b*3200;
    for (int i=t;i<3200;i+=256) s2[i]=src[i];
    if (t<16){ redS[t]=0.f; redQ[t]=0.f; }
    __syncthreads();
    for (int i=t;i<800;i+=256){
        int c=i&15, hh=i>>4;            // y2 layout [h][c]
        float a=g_a2[c], d=g_d2[c];
        const float* p=&s2[(hh*4)*16+c];
        t1[c*50+hh]=fmaxf(fmaxf(fmaf(a,p[0],d),fmaf(a,p[16],d)),
                          fmaxf(fmaf(a,p[32],d),fmaf(a,p[48],d)));
    }
    __syncthreads();
    for (int i=t;i<800;i+=256){
        int oc=i/50, h=i%50, g=oc>>1;
        float acc=c3b[oc];
        #pragma unroll
        for (int ic2=0;ic2<2;ic2++){
            const float* wr=c3w+(oc*2+ic2)*25;
            const float* tr=t1+(g*2+ic2)*50;
            #pragma unroll
            for (int k=0;k<25;k++){
                int hp=h+k-12;
                if (hp>=0 && hp<50) acc=fmaf(wr[k],tr[hp],acc);
            }
        }
        u[i]=eluf(acc);
    }
    __syncthreads();
    for (int i=t;i<800;i+=256){
        int o=i/50, h=i%50;
        float acc=cpb[o];
        #pragma unroll
        for (int k=0;k<16;k++) acc=fmaf(cpw[o*16+k],u[k*50+h],acc);
        float v=eluf(acc);
        g_y3[b*800+o*50+h]=v;
        atomicAdd(&redS[o],v); atomicAdd(&redQ[o],v*v);
    }
    __syncthreads();
    if (t<16){
        int slot=b&255;
        atomicAdd(&g_p3[slot][t*2],(double)redS[t]);
        atomicAdd(&g_p3[slot][t*2+1],(double)redQ[t]);
    }
}

// ---------- k7: LSTM, f32x2 gate dots. fwd full scan; bwd is ONE step ----------
__global__ void __launch_bounds__(128) k7_lstm(const float* __restrict__ wih,
                                               const float* __restrict__ whh,
                                               const float* __restrict__ bih,
                                               const float* __restrict__ bhh){
    extern __shared__ float sm[];
    float* whhs = sm;            // 200*52 = 10400
    float* wihs = sm+10400;      // 200
    float* biass= sm+10600;      // 200
    float* gates= sm+10800;      // 32*200 = 6400
    float* hsm  = sm+17200;      // 1600
    float* csm  = sm+18800;      // 1600
    float* xsm  = sm+20400;      // 800  -> 21200 floats = 84800 B
    int c=blockIdx.x>>5, b0=(blockIdx.x&31)<<5, t=threadIdx.x;
    int base=(c*2)*200;

    for (int i=t;i<10000;i+=128){ int j=i/50,k=i%50; whhs[j*52+k]=whh[(base+j)*50+k]; }
    for (int i=t;i<200;i+=128){ wihs[i]=wih[base+i]; biass[i]=bih[base+i]+bhh[base+i]; }
    {
        float a3=g_a3[c], d3=g_d3[c];
        for (int i=t;i<800;i+=128){
            int r=i/25, tt=i%25;
            const float* yp=g_y3+((b0+r)*16+c)*50;
            xsm[i]=fmaxf(fmaf(a3,yp[2*tt],d3), fmaf(a3,yp[2*tt+1],d3));
        }
    }
    for (int i=t;i<1600;i+=128){ hsm[i]=0.f; csm[i]=0.f; }
    __syncthreads();

    int r=t>>2, q=t&3;
    float sA=(q==2)?2.f:1.f, mq=(q==2)?2.f:1.f, cq=(q==2)?-1.f:0.f;
    unsigned wbase=(unsigned)__cvta_generic_to_shared(whhs);
    float* grow=gates+r*200;
    for (int step=0;step<25;step++){
        unsigned long long hr2[25];
        const unsigned long long* hp=(const unsigned long long*)(hsm+r*50);
        #pragma unroll
        for (int k=0;k<25;k++) hr2[k]=hp[k];
        float xv=xsm[r*25+step];
        #pragma unroll 2
        for (int jj=0;jj<50;jj++){
            int j=q*50+jj;
            unsigned a=wbase+(unsigned)j*208u;
            unsigned long long acc0=0ULL, acc1=0ULL;
            #pragma unroll
            for (int k4=0;k4<12;k4++){
                unsigned long long wa,wb;
                asm("ld.shared.v2.u64 {%0,%1},[%2];":"=l"(wa),"=l"(wb):"r"(a+k4*16));
                asm("fma.rn.f32x2 %0,%1,%2,%0;":"+l"(acc0):"l"(hr2[2*k4]),"l"(wa));
                asm("fma.rn.f32x2 %0,%1,%2,%0;":"+l"(acc1):"l"(hr2[2*k4+1]),"l"(wb));
            }
            {
                unsigned long long wc;
                asm("ld.shared.u64 %0,[%1];":"=l"(wc):"r"(a+192));
                asm("fma.rn.f32x2 %0,%1,%2,%0;":"+l"(acc0):"l"(hr2[24]),"l"(wc));
            }
            float x0,x1,y0,y1;
            asm("mov.b64 {%0,%1},%2;":"=f"(x0),"=f"(x1):"l"(acc0));
            asm("mov.b64 {%0,%1},%2;":"=f"(y0),"=f"(y1):"l"(acc1));
            float acc=(x0+x1)+(y0+y1)+fmaf(xv,wihs[j],biass[j]);
            float rr_=1.f/(1.f+__expf(-acc*sA));
            grow[j]=fmaf(rr_,mq,cq);
        }
        __syncthreads();
        for (int i=t;i<1600;i+=128){
            int rr=i/50, k=i%50;
            const float* gr=gates+rr*200;
            float cn=fmaf(gr[50+k],csm[i],gr[k]*gr[100+k]);
            csm[i]=cn;
            float hn=gr[150+k]*tanhfast(cn);
            hsm[i]=hn;
            if (step==24) g_feat[(c*100+k)*1024 + b0+rr]=hn;
        }
        __syncthreads();
    }
    // backward direction: only first step of reversed scan used
    int bb=(c*2+1)*200;
    for (int i=t;i<1600;i+=128){
        int rr=i/50, k=i%50;
        float xv=xsm[rr*25+24];
        float ig=sigm    (fmaf(xv,wih[bb+k],     bih[bb+k]     +bhh[bb+k]));
        float gg=tanhfast(fmaf(xv,wih[bb+100+k], bih[bb+100+k]+bhh[bb+100+k]));
        float oo=sigm    (fmaf(xv,wih[bb+150+k], bih[bb+150+k]+bhh[bb+150+k]));
        g_feat[(c*100+50+k)*1024 + b0+rr]=oo*tanhfast(ig*gg);
    }
}

// ---------- k8: per-channel head BN + linear + sigmoid (1024 threads) ----------
__global__ void __launch_bounds__(1024) k8_head(const float* __restrict__ hbnw,
                                                const float* __restrict__ hbnb,
                                                const float* __restrict__ hlw,
                                                const float* __restrict__ hlb){
    __shared__ float coef[100], dsum[32];
    __shared__ float Cs;
    int c=blockIdx.x, t=threadIdx.x, lane=t&31, w=t>>5;
    float dacc=0.f;
    for (int f=w; f<100; f+=32){
        const float* p=g_feat+(c*100+f)*1024;
        float s=0.f,q=0.f;
        #pragma unroll 4
        for (int j=lane;j<1024;j+=32){ float v=p[j]; s+=v; q+=v*v; }
        for (int off=16;off;off>>=1){
            s+=__shfl_xor_sync(0xffffffffu,s,off);
            q+=__shfl_xor_sync(0xffffffffu,q,off);
        }
        if (lane==0){
            float m=s*(1.f/1024.f), var=q*(1.f/1024.f)-m*m;
            float a=hbnw[c*100+f]*rsqrtf(var);
            float d=hbnb[c*100+f]-m*a;
            float lw=hlw[c*100+f];
            coef[f]=a*lw;
            dacc+=d*lw;
        }
    }
    if (lane==0) dsum[w]=dacc;
    __syncthreads();
    if (t==0){
        float s=hlb[c];
        #pragma unroll
        for (int i=0;i<32;i++) s+=dsum[i];
        Cs=s;
    }
    __syncthreads();
    float acc=Cs;
    #pragma unroll 4
    for (int f=0;f<100;f++) acc=fmaf(g_feat[(c*100+f)*1024+t],coef[f],acc);
    g_y[t*16+c]=sigm(acc);
}

// ---------- k9: final BN over batch + linear + sigmoid ----------
__global__ void k9_final(const float* __restrict__ fbnw, const float* __restrict__ fbnb,
                         const float* __restrict__ flw,  const float* __restrict__ flb,
                         float* __restrict__ out){
    __shared__ float ss[16], sq[16], cf[16];
    __shared__ float Cs;
    int t=threadIdx.x, lane=t&31;
    if (t<16){ ss[t]=0.f; sq[t]=0.f; }
    __syncthreads();
    float yv[16];
    #pragma unroll
    for (int c=0;c<16;c++) yv[c]=g_y[t*16+c];
    #pragma unroll
    for (int c=0;c<16;c++){
        float s=yv[c], q=yv[c]*yv[c];
        for (int off=16;off;off>>=1){
            s+=__shfl_xor_sync(0xffffffffu,s,off);
            q+=__shfl_xor_sync(0xffffffffu,q,off);
        }
        if (lane==0){ atomicAdd(&ss[c],s); atomicAdd(&sq[c],q); }
    }
    __syncthreads();
    if (t<16){
        float m=ss[t]*(1.f/1024.f), var=sq[t]*(1.f/1024.f)-m*m;
        float a=fbnw[t]*rsqrtf(var);
        float d=fbnb[t]-m*a;
        cf[t]=a*flw[t];
        ss[t]=d*flw[t];
    }
    __syncthreads();
    if (t==0){
        float s=flb[0];
        #pragma unroll
        for (int c=0;c<16;c++) s+=ss[c];
        Cs=s;
    }
    __syncthreads();
    float acc=Cs;
    #pragma unroll
    for (int c=0;c<16;c++) acc=fmaf(yv[c],cf[c],acc);
    out[t]=sigm(acc);
}

extern "C" void kernel_launch(void* const* d_in, const int* in_sizes, int n_in,
                              void* d_out, int out_size){
    const float* x    =(const float*)d_in[0];
    const float* c1w  =(const float*)d_in[1];
    const float* c1b  =(const float*)d_in[2];
    const float* bn1w =(const float*)d_in[3];
    const float* bn1b =(const float*)d_in[4];
    const float* c2w  =(const float*)d_in[5];
    const float* c2b  =(const float*)d_in[6];
    const float* bn2w =(const float*)d_in[7];
    const float* bn2b =(const float*)d_in[8];
    const float* c3w  =(const float*)d_in[9];
    const float* c3b  =(const float*)d_in[10];
    const float* bn3w =(const float*)d_in[11];
    const float* bn3b =(const float*)d_in[12];
    const float* cpw  =(const float*)d_in[13];
    const float* cpb  =(const float*)d_in[14];
    const float* wih  =(const float*)d_in[15];
    const float* whh  =(const float*)d_in[16];
    const float* bih  =(const float*)d_in[17];
    const float* bhh  =(const float*)d_in[18];
    const float* hbnw =(const float*)d_in[19];
    const float* hbnb =(const float*)d_in[20];
    const float* hlw  =(const float*)d_in[21];
    const float* hlb  =(const float*)d_in[22];
    const float* fbnw =(const float*)d_in[23];
    const float* fbnb =(const float*)d_in[24];
    const float* flw  =(const float*)d_in[25];
    const float* flb  =(const float*)d_in[26];
    float* out=(float*)d_out;

    cudaFuncSetAttribute(k7_lstm, cudaFuncAttributeMaxDynamicSharedMemorySize, 84800);

    kZ<<<80,256>>>();
    k1_conv1<<<dim3(8,1024), dim3(32,5)>>>(x,c1w,c1b);
    k2_setup<<<1,256>>>(bn1w,bn1b,c2w,c2b);
    k3_conv2<<<1024,256>>>();
    k3b_stats<<<256,256>>>();
    k4_bn2<<<1,32>>>(bn2w,bn2b);
    k5_conv3p<<<1024,256>>>(c3w,c3b,cpw,cpb);
    k6_bn3<<<1,32>>>(bn3w,bn3b);
    k7_lstm<<<512,128,84800>>>(wih,whh,bih,bhh);
    k8_head<<<16,1024>>>(hbnw,hbnb,hlw,hlb);
    k9_final<<<1,1024>>>(fbnw,fbnb,flw,flb,out);
}